// round 11
// baseline (speedup 1.0000x reference)
#include <cuda_runtime.h>
#include <cstdint>
#include <math.h>

// Causal self-attention, B=4, S=4096, D=64, fp32.
// Tensor-core flash attention (mma.sync m16n8k8 tf32) + split-K.
// R11: 256-thread CTAs, 8 warps = 4 row-pairs x 2 key-halves. Each warp:
// 16 rows x 32 keys -> s[4][4], small reg footprint -> 2 CTAs/SM = 16 warps.
// Key-halves produce independent partials (8 combine slots = 4 splits x 2).

#define BB 4
#define SS 4096
#define DHH 64
#define BMM 64
#define NTHREADS 256
#define SPLITS 4
#define NSLOT (SPLITS * 2)
#define NROWS (BB * SS)

// smem (floats): K raw [8][4][132]=4224 (P overlays 8 warps x 512),
// V tf32 [8][4][132]=4224, Q frag tables 4 x 1024 = 4096.
#define OFF_K 0
#define OFF_V 4224
#define OFF_QF 8448
#define SMEM_FLOATS 12544
#define SMEM_BYTES (SMEM_FLOATS * 4)

__device__ float g_pO[NSLOT * NROWS * DHH];
__device__ float g_ml[NSLOT * NROWS * 2];

__device__ __forceinline__ float ex2a(float x) {
    float y; asm("ex2.approx.f32 %0,%1;" : "=f"(y) : "f"(x)); return y;
}
__device__ __forceinline__ void split2(float f, float& hi, float& lo) {
    hi = __uint_as_float(__float_as_uint(f) & 0xffffe000u);
    lo = f - hi;
}
__device__ __forceinline__ float tf32_rna(float x) {
    unsigned y;
    asm("cvt.rna.tf32.f32 %0, %1;" : "=r"(y) : "f"(x));
    return __uint_as_float(y);
}

__device__ __forceinline__ void mma_tf32(float c[4],
        float a0, float a1, float a2, float a3, float b0, float b1) {
    asm("mma.sync.aligned.m16n8k8.row.col.f32.tf32.tf32.f32 "
        "{%0,%1,%2,%3},{%4,%5,%6,%7},{%8,%9},{%0,%1,%2,%3};"
        : "+f"(c[0]), "+f"(c[1]), "+f"(c[2]), "+f"(c[3])
        : "r"(__float_as_uint(a0)), "r"(__float_as_uint(a1)),
          "r"(__float_as_uint(a2)), "r"(__float_as_uint(a3)),
          "r"(__float_as_uint(b0)), "r"(__float_as_uint(b1)));
}
__device__ __forceinline__ void mma3(float c[4],
        const float ah[4], const float al[4],
        float bh0, float bh1, float bl0, float bl1) {
    mma_tf32(c, ah[0], ah[1], ah[2], ah[3], bh0, bh1);
    mma_tf32(c, al[0], al[1], al[2], al[3], bh0, bh1);
    mma_tf32(c, ah[0], ah[1], ah[2], ah[3], bl0, bl1);
}
__device__ __forceinline__ void split4(const float4& v, float h[4], float l[4]) {
    split2(v.x, h[0], l[0]); split2(v.y, h[1], l[1]);
    split2(v.z, h[2], l[2]); split2(v.w, h[3], l[3]);
}

__global__ __launch_bounds__(NTHREADS, 2)
void fa_mma_split(const float* __restrict__ Q, const float* __restrict__ K,
                  const float* __restrict__ V) {
    extern __shared__ float sm[];
    const int idx   = blockIdx.x;
    const int split = idx & (SPLITS - 1);
    const int rest  = idx >> 2;
    const int b     = rest & 3;
    const int qt    = (SS / BMM) - 1 - (rest >> 2);   // heavy q-tiles first
    const int tid   = threadIdx.x;
    const int wid   = tid >> 5;            // 0..7
    const int lane  = tid & 31;
    const int pairId = wid >> 1;           // row group 0..3
    const int h      = wid & 1;            // key half 0/1
    const int gg    = lane >> 2;
    const int c4    = lane & 3;
    const int rA0 = qt * BMM + pairId * 16 + gg;
    const int rA1 = rA0 + 8;

    const int sidx = split * 2 + h;
    float* po  = g_pO + ((size_t)sidx * NROWS) * DHH;
    float* pml = g_ml + ((size_t)sidx * NROWS) * 2;
    const int rowg_cta = b * SS + qt * BMM;

    const int len = (qt + SPLITS) / SPLITS;     // ceil((qt+1)/SPLITS)
    const int t0  = split * len;
    const int t1  = min(t0 + len, qt + 1);

    if (t0 >= t1) {   // empty split: neutral partials for BOTH key-half slots
#pragma unroll
        for (int sl = 0; sl < 2; sl++) {
            float* poe  = g_pO + ((size_t)(split * 2 + sl) * NROWS) * DHH;
            float* pmle = g_ml + ((size_t)(split * 2 + sl) * NROWS) * 2;
            for (int i = tid; i < BMM * DHH; i += NTHREADS)
                poe[(size_t)(rowg_cta + (i >> 6)) * DHH + (i & 63)] = 0.f;
            if (tid < BMM) {
                pmle[(size_t)(rowg_cta + tid) * 2 + 0] = -INFINITY;
                pmle[(size_t)(rowg_cta + tid) * 2 + 1] = 0.f;
            }
        }
        return;
    }

    // ---- stage Q tile raw (K region), even warps build the 4 frag tables
    {
        const float4* qg4 = (const float4*)(Q + ((size_t)b * SS + qt * BMM) * DHH);
        float4* qs4 = (float4*)sm;
#pragma unroll
        for (int i = 0; i < 4; i++) qs4[i * NTHREADS + tid] = qg4[i * NTHREADS + tid];
        __syncthreads();
        if (h == 0) {
            const float qscale = 0.125f * 1.44269504088896f;  // 1/sqrt(64)*log2(e)
            const int lr0 = pairId * 16 + gg, lr1 = lr0 + 8;
            float* qf = sm + OFF_QF + pairId * 1024;
#pragma unroll
            for (int t = 0; t < 8; t++) {
                float v0 = sm[lr0 * 64 + 8 * t + c4]     * qscale;
                float v1 = sm[lr1 * 64 + 8 * t + c4]     * qscale;
                float v2 = sm[lr0 * 64 + 8 * t + c4 + 4] * qscale;
                float v3 = sm[lr1 * 64 + 8 * t + c4 + 4] * qscale;
                *(float4*)&qf[t * 128 + lane * 4] = make_float4(v0, v1, v2, v3);
            }
        }
        __syncthreads();   // raw Q may now be overwritten by K staging
    }

    float o[8][4];
#pragma unroll
    for (int nn = 0; nn < 8; nn++)
#pragma unroll
        for (int c = 0; c < 4; c++) o[nn][c] = 0.f;
    float m0 = -INFINITY, m1 = -INFINITY, l0 = 0.f, l1 = 0.f;

    for (int kt = t0; kt < t1; kt++) {
        const bool masked = (kt == qt);

        // ---- stage K raw into frag-ordered layout (256 threads, 4 each)
        const float4* kg4 = (const float4*)(K + ((size_t)b * SS + kt * 64) * DHH);
        const float4* vg4 = (const float4*)(V + ((size_t)b * SS + kt * 64) * DHH);
#pragma unroll
        for (int i = 0; i < 4; i++) {
            int e = i * NTHREADS + tid;
            float4 kv = kg4[e];
            int n = e >> 4, dbase = (e & 15) << 2;
            int base = (n >> 3) * 528 + (dbase >> 4) * 132
                     + ((n & 7) * 4) * 4 + ((dbase >> 2) & 3);
            sm[OFF_K + base +  0] = kv.x;
            sm[OFF_K + base +  4] = kv.y;
            sm[OFF_K + base +  8] = kv.z;
            sm[OFF_K + base + 12] = kv.w;
        }
        // ---- stage V pre-rounded to tf32
#pragma unroll
        for (int i = 0; i < 4; i++) {
            int e = i * NTHREADS + tid;
            float4 vv = vg4[e];
            int n = e >> 4, dbase = (e & 15) << 2;
            int kk = n >> 3, rem = n & 7;
            int jel = (rem >> 2) + 2 * ((dbase >> 3) & 1);
            int base = kk * 528 + (dbase >> 4) * 132 + (rem & 3) * 4;
            float vals[4] = {vv.x, vv.y, vv.z, vv.w};
#pragma unroll
            for (int jj = 0; jj < 4; jj++) {
                int d = dbase + jj;
                sm[OFF_V + base + ((d & 7) * 4) * 4 + jel] = tf32_rna(vals[jj]);
            }
        }
        __syncthreads();

        // ---- S = Q K^T over this warp's 4 key n-tiles (nn = h*4 + nl)
        float s[4][4];
#pragma unroll
        for (int nl = 0; nl < 4; nl++)
#pragma unroll
            for (int c = 0; c < 4; c++) s[nl][c] = 0.f;
        const float* qf = sm + OFF_QF + pairId * 1024;
#pragma unroll
        for (int u = 0; u < 4; u++) {
            float4 q0 = *(const float4*)&qf[(2 * u)     * 128 + lane * 4];
            float4 q1 = *(const float4*)&qf[(2 * u + 1) * 128 + lane * 4];
            float q0h[4], q0l[4], q1h[4], q1l[4];
            split4(q0, q0h, q0l);
            split4(q1, q1h, q1l);
#pragma unroll
            for (int nl = 0; nl < 4; nl++) {
                int nn = h * 4 + nl;
                float4 kr = *(const float4*)&sm[OFF_K + nn * 528 + u * 132 + lane * 4];
                float kh[4], kl[4];
                split4(kr, kh, kl);
                mma3(s[nl], q0h, q0l, kh[0], kh[1], kl[0], kl[1]);
                mma3(s[nl], q1h, q1l, kh[2], kh[3], kl[2], kl[3]);
            }
        }
        __syncthreads();   // all K reads done; P may overlay the K region

        if (masked) {
#pragma unroll
            for (int nl = 0; nl < 4; nl++) {
                int kb = kt * 64 + (h * 4 + nl) * 8 + 2 * c4;
                if (kb     > rA0) s[nl][0] = -1e30f;
                if (kb + 1 > rA0) s[nl][1] = -1e30f;
                if (kb     > rA1) s[nl][2] = -1e30f;
                if (kb + 1 > rA1) s[nl][3] = -1e30f;
            }
        }

        // ---- online softmax over this warp's 32 keys
        float x0 = s[0][0], x1 = s[0][2];
#pragma unroll
        for (int nl = 0; nl < 4; nl++) {
            x0 = fmaxf(x0, fmaxf(s[nl][0], s[nl][1]));
            x1 = fmaxf(x1, fmaxf(s[nl][2], s[nl][3]));
        }
        x0 = fmaxf(x0, __shfl_xor_sync(0xffffffffu, x0, 1));
        x0 = fmaxf(x0, __shfl_xor_sync(0xffffffffu, x0, 2));
        x1 = fmaxf(x1, __shfl_xor_sync(0xffffffffu, x1, 1));
        x1 = fmaxf(x1, __shfl_xor_sync(0xffffffffu, x1, 2));
        float nm0 = fmaxf(m0, x0), nm1 = fmaxf(m1, x1);
        float sc0 = ex2a(m0 - nm0), sc1 = ex2a(m1 - nm1);
        m0 = nm0; m1 = nm1;
        l0 *= sc0; l1 *= sc1;
        float u0 = 0.f, u1 = 0.f;
#pragma unroll
        for (int nl = 0; nl < 4; nl++) {
            s[nl][0] = tf32_rna(ex2a(s[nl][0] - m0));
            s[nl][1] = tf32_rna(ex2a(s[nl][1] - m0));
            s[nl][2] = tf32_rna(ex2a(s[nl][2] - m1));
            s[nl][3] = tf32_rna(ex2a(s[nl][3] - m1));
            u0 += s[nl][0] + s[nl][1];
            u1 += s[nl][2] + s[nl][3];
        }
        u0 += __shfl_xor_sync(0xffffffffu, u0, 1);
        u0 += __shfl_xor_sync(0xffffffffu, u0, 2);
        u1 += __shfl_xor_sync(0xffffffffu, u1, 1);
        u1 += __shfl_xor_sync(0xffffffffu, u1, 2);
        l0 += u0; l1 += u1;
#pragma unroll
        for (int nn = 0; nn < 8; nn++) {
            o[nn][0] *= sc0; o[nn][1] *= sc0;
            o[nn][2] *= sc1; o[nn][3] *= sc1;
        }

        // ---- P (tf32) -> per-warp overlay of K region, a-frag order
        float* wP = sm + OFF_K + wid * 512;
#pragma unroll
        for (int nl = 0; nl < 4; nl++) {
#pragma unroll
            for (int ci = 0; ci < 4; ci++) {
                int cc   = 2 * c4 + (ci & 1);
                int slot = ((cc >= 4) ? 2 : 0) + ((ci >= 2) ? 1 : 0);
                int lamp = gg * 4 + (cc & 3);
                wP[nl * 128 + lamp * 4 + slot] = s[nl][ci];
            }
        }
        __syncwarp();

        // ---- O += P V over this warp's 4 key k-tiles
#pragma unroll
        for (int kkl = 0; kkl < 4; kkl++) {
            float4 pr = *(const float4*)&wP[kkl * 128 + lane * 4];
            int kk = h * 4 + kkl;
#pragma unroll
            for (int w = 0; w < 4; w++) {
                float4 vr = *(const float4*)&sm[OFF_V + kk * 528 + w * 132 + lane * 4];
                mma_tf32(o[2 * w],     pr.x, pr.y, pr.z, pr.w, vr.x, vr.y);
                mma_tf32(o[2 * w + 1], pr.x, pr.y, pr.z, pr.w, vr.z, vr.w);
            }
        }
        __syncthreads();    // P/V regions free before next tile's staging
    }

    // ---- write partials (unnormalized O + per-row m,l) to this warp's slot
    const int g0 = b * SS + rA0, g1 = b * SS + rA1;
#pragma unroll
    for (int nn = 0; nn < 8; nn++) {
        int col = nn * 8 + 2 * c4;
        *(float2*)&po[(size_t)g0 * DHH + col] = make_float2(o[nn][0], o[nn][1]);
        *(float2*)&po[(size_t)g1 * DHH + col] = make_float2(o[nn][2], o[nn][3]);
    }
    if (c4 == 0) {
        pml[(size_t)g0 * 2 + 0] = m0; pml[(size_t)g0 * 2 + 1] = l0;
        pml[(size_t)g1 * 2 + 0] = m1; pml[(size_t)g1 * 2 + 1] = l1;
    }
}

// Merge the 8 partials per row.
__global__ __launch_bounds__(256)
void fa_combine_kernel(float* __restrict__ O) {
    const int gid  = blockIdx.x * 256 + threadIdx.x;
    const int part = gid & 3;
    const int row  = gid >> 2;

    float mv[NSLOT], lv[NSLOT];
#pragma unroll
    for (int s = 0; s < NSLOT; s++) {
        mv[s] = g_ml[((size_t)s * NROWS + row) * 2 + 0];
        lv[s] = g_ml[((size_t)s * NROWS + row) * 2 + 1];
    }
    float M = mv[0];
#pragma unroll
    for (int s = 1; s < NSLOT; s++) M = fmaxf(M, mv[s]);
    float w[NSLOT], L = 0.f;
#pragma unroll
    for (int s = 0; s < NSLOT; s++) {
        w[s] = ex2a(mv[s] - M);
        L += w[s] * lv[s];
    }
    const float inv = 1.f / L;

    float4 acc[4];
#pragma unroll
    for (int i = 0; i < 4; i++) acc[i] = make_float4(0.f, 0.f, 0.f, 0.f);
#pragma unroll
    for (int s = 0; s < NSLOT; s++) {
        const float4* p = (const float4*)(
            g_pO + ((size_t)s * NROWS + row) * DHH + part * 16);
        float ws = w[s];
#pragma unroll
        for (int i = 0; i < 4; i++) {
            float4 v = p[i];
            acc[i].x = fmaf(ws, v.x, acc[i].x);
            acc[i].y = fmaf(ws, v.y, acc[i].y);
            acc[i].z = fmaf(ws, v.z, acc[i].z);
            acc[i].w = fmaf(ws, v.w, acc[i].w);
        }
    }
    float4* out = (float4*)(O + (size_t)row * DHH + part * 16);
#pragma unroll
    for (int i = 0; i < 4; i++) {
        float4 v = acc[i];
        v.x *= inv; v.y *= inv; v.z *= inv; v.w *= inv;
        out[i] = v;
    }
}

extern "C" void kernel_launch(void* const* d_in, const int* in_sizes, int n_in,
                              void* d_out, int out_size) {
    const float* Q = (const float*)d_in[0];
    const float* K = (const float*)d_in[1];
    const float* V = (const float*)d_in[2];
    float* O = (float*)d_out;

    cudaFuncSetAttribute(fa_mma_split,
                         cudaFuncAttributeMaxDynamicSharedMemorySize, SMEM_BYTES);
    const int grid = SPLITS * BB * (SS / BMM);   // 1024 CTAs
    fa_mma_split<<<grid, NTHREADS, SMEM_BYTES>>>(Q, K, V);
    fa_combine_kernel<<<NROWS * 4 / 256, 256>>>(O);
}